// round 1
// baseline (speedup 1.0000x reference)
#include <cuda_runtime.h>
#include <cuda_bf16.h>

// Problem constants
#define NS 128          // shapelets
#define ND 3            // channels
#define NL 16           // shapelet length
#define NK (ND*NL)      // 48 = reduction dim
#define NH 512          // hidden
#define NC 10           // classes
#define NB 32           // batch
#define NT 16384        // time
#define TV (NT - NL + 1)   // 16369 valid positions
#define TCHUNK 128
#define NCHUNK ((TV + TCHUNK - 1) / TCHUNK)   // 128

// Block-partial min scratch: [B*NCHUNK][NS]  (32*128*128 floats = 2 MB)
__device__ float g_partial[NB * NCHUNK * NS];

// ---------------------------------------------------------------------------
// Kernel 1: fused cross-corr + window-energy + distance + per-chunk min
// Block tile: 128 shapelets x 128 positions; thread microtile 8x8.
// ---------------------------------------------------------------------------
__global__ __launch_bounds__(256, 2)
void dist_kernel(const float* __restrict__ x, const float* __restrict__ shp)
{
    __shared__ float sh[NK][NS];              // shapelets transposed [k][s]  24 KB
    __shared__ float xs[ND][TCHUNK + NL];     // x tile + halo
    __shared__ float ssq[NS];                 // ||shapelet||^2
    __shared__ float wsq[TCHUNK];             // window energy
    __shared__ int   smin[NS];                // per-block min (float bits)

    const int bid   = blockIdx.x;
    const int b     = bid / NCHUNK;
    const int chunk = bid % NCHUNK;
    const int t0    = chunk * TCHUNK;
    const int tid   = threadIdx.x;

    // Load shapelets transposed: g[s*48 + k] -> sh[k][s]
    for (int i = tid; i < NS * NK; i += 256) {
        int s = i / NK, k = i % NK;
        sh[k][s] = shp[i];
    }
    // Load x tile (+halo), zero-pad past T
    for (int i = tid; i < ND * (TCHUNK + NL); i += 256) {
        int d = i / (TCHUNK + NL), j = i % (TCHUNK + NL);
        int tg = t0 + j;
        xs[d][j] = (tg < NT) ? x[(b * ND + d) * NT + tg] : 0.0f;
    }
    if (tid < NS) smin[tid] = 0x7F800000;   // +inf
    __syncthreads();

    // ssq (threads 0..127), wsq (threads 128..255)
    if (tid < NS) {
        float a = 0.0f;
        #pragma unroll 8
        for (int k = 0; k < NK; k++) { float v = sh[k][tid]; a = fmaf(v, v, a); }
        ssq[tid] = a;
    } else {
        int j = tid - 128;
        float a = 0.0f;
        #pragma unroll
        for (int d = 0; d < ND; d++)
            #pragma unroll
            for (int l = 0; l < NL; l++) { float v = xs[d][j + l]; a = fmaf(v, v, a); }
        wsq[j] = a;
    }
    __syncthreads();

    const int ts = tid & 15;        // shapelet group (16)
    const int tt = tid >> 4;        // t group (16)
    const int sb = ts * 8;
    const int tb = tt * 8;

    float acc[8][8];
    #pragma unroll
    for (int j = 0; j < 8; j++)
        #pragma unroll
        for (int i = 0; i < 8; i++) acc[j][i] = 0.0f;

    #pragma unroll
    for (int d = 0; d < ND; d++) {
        #pragma unroll 4
        for (int l = 0; l < NL; l++) {
            const int k = d * NL + l;
            const float4 A  = *(const float4*)&sh[k][sb];
            const float4 Bv = *(const float4*)&sh[k][sb + 4];
            float sv[8] = {A.x, A.y, A.z, A.w, Bv.x, Bv.y, Bv.z, Bv.w};
            float xv[8];
            #pragma unroll
            for (int j = 0; j < 8; j++) xv[j] = xs[d][tb + l + j];
            #pragma unroll
            for (int j = 0; j < 8; j++)
                #pragma unroll
                for (int i = 0; i < 8; i++)
                    acc[j][i] = fmaf(xv[j], sv[i], acc[j][i]);
        }
    }

    // distance + local min over this thread's 8 t-positions
    float dmin[8];
    #pragma unroll
    for (int i = 0; i < 8; i++) dmin[i] = __int_as_float(0x7F800000);

    #pragma unroll
    for (int j = 0; j < 8; j++) {
        const int tg = t0 + tb + j;
        const bool valid = (tg < TV);
        const float w = wsq[tb + j];
        #pragma unroll
        for (int i = 0; i < 8; i++) {
            float dist = w + ssq[sb + i] - 2.0f * acc[j][i];
            if (valid) dmin[i] = fminf(dmin[i], dist);
        }
    }
    // shared-memory min across the 16 t-groups (positive floats: int order == float order)
    #pragma unroll
    for (int i = 0; i < 8; i++)
        atomicMin(&smin[sb + i], __float_as_int(dmin[i]));
    __syncthreads();

    if (tid < NS)
        g_partial[bid * NS + tid] = __int_as_float(smin[tid]);
}

// ---------------------------------------------------------------------------
// Kernel 2: reduce per-chunk mins -> distance[b][s] in d_out[0 .. B*S)
// ---------------------------------------------------------------------------
__global__ void reduce_kernel(float* __restrict__ out)
{
    const int b = blockIdx.x;
    const int s = threadIdx.x;
    float m = __int_as_float(0x7F800000);
    #pragma unroll 4
    for (int c = 0; c < NCHUNK; c++)
        m = fminf(m, g_partial[(b * NCHUNK + c) * NS + s]);
    out[b * NS + s] = m;
}

// ---------------------------------------------------------------------------
// Kernel 3: MLP head.  One block per batch row, 512 threads.
// ---------------------------------------------------------------------------
__global__ __launch_bounds__(512)
void mlp_kernel(float* __restrict__ out,
                const float* __restrict__ W1, const float* __restrict__ b1,
                const float* __restrict__ W2, const float* __restrict__ b2)
{
    __shared__ float sd[NS];
    __shared__ float hbuf[NH];
    __shared__ float wpart[16];

    const int b   = blockIdx.x;
    const int tid = threadIdx.x;

    if (tid < NS) sd[tid] = out[b * NS + tid];
    __syncthreads();

    // h[tid] = relu(dot(distance_row, W1[tid]) + b1[tid])
    float a = b1[tid];
    #pragma unroll 8
    for (int k = 0; k < NS; k++)
        a = fmaf(sd[k], W1[tid * NS + k], a);
    hbuf[tid] = fmaxf(a, 0.0f);
    __syncthreads();

    const int lane = tid & 31;
    const int warp = tid >> 5;
    float* cls = out + NB * NS;

    for (int c = 0; c < NC; c++) {
        float p = hbuf[tid] * W2[c * NH + tid];
        #pragma unroll
        for (int o = 16; o > 0; o >>= 1)
            p += __shfl_down_sync(0xFFFFFFFFu, p, o);
        if (lane == 0) wpart[warp] = p;
        __syncthreads();
        if (tid < 16) {
            float q = wpart[tid];
            #pragma unroll
            for (int o = 8; o > 0; o >>= 1)
                q += __shfl_down_sync(0xFFFFu, q, o);
            if (tid == 0) cls[b * NC + c] = q + b2[c];
        }
        __syncthreads();
    }
}

// ---------------------------------------------------------------------------
extern "C" void kernel_launch(void* const* d_in, const int* in_sizes, int n_in,
                              void* d_out, int out_size)
{
    const float* x   = (const float*)d_in[0];
    const float* shp = (const float*)d_in[1];
    const float* W1  = (const float*)d_in[2];
    const float* b1  = (const float*)d_in[3];
    const float* W2  = (const float*)d_in[4];
    const float* b2  = (const float*)d_in[5];
    float* out = (float*)d_out;

    dist_kernel<<<NB * NCHUNK, 256>>>(x, shp);
    reduce_kernel<<<NB, NS>>>(out);
    mlp_kernel<<<NB, NH>>>(out, W1, b1, W2, b2);
}

// round 5
// speedup vs baseline: 1.8097x; 1.8097x over previous
#include <cuda_runtime.h>
#include <cuda_bf16.h>
#include <cstdint>

// ---------------- problem constants ----------------
#define NS 128          // shapelets
#define ND 3            // channels
#define NL 16           // shapelet length
#define NK 48           // K = ND*NL
#define NH 512          // hidden
#define NC 10           // classes
#define NB 32           // batch
#define NT 16384        // time
#define TV (NT - NL + 1)   // 16369 valid positions
#define TCH 128
#define NCHUNK 128
#define XS_LEN (TCH + NL)  // 144
#define APAD 52            // stride 52 floats == 20 mod 32 -> conflict-free frag loads

// ---------------- helpers ----------------
__device__ __forceinline__ uint32_t f2tf32(float f) {
    uint32_t r;
    asm("cvt.rna.tf32.f32 %0, %1;" : "=r"(r) : "f"(f));
    return r;
}

__device__ __forceinline__ void mma_tf32(float d[4], const uint32_t a[4], const uint32_t b[2]) {
    asm volatile(
        "mma.sync.aligned.m16n8k8.row.col.f32.tf32.tf32.f32 "
        "{%0,%1,%2,%3}, {%4,%5,%6,%7}, {%8,%9}, {%0,%1,%2,%3};"
        : "+f"(d[0]), "+f"(d[1]), "+f"(d[2]), "+f"(d[3])
        : "r"(a[0]), "r"(a[1]), "r"(a[2]), "r"(a[3]), "r"(b[0]), "r"(b[1]));
}

// ---------------------------------------------------------------------------
// init: distance slots to +inf bits (positive floats: int order == float order)
// ---------------------------------------------------------------------------
__global__ void init_kernel(float* __restrict__ out) {
    int i = blockIdx.x * 256 + threadIdx.x;
    if (i < NB * NS) ((int*)out)[i] = 0x7F800000;
}

// ---------------------------------------------------------------------------
// dist: one block per (batch, 128-t chunk). 128x128xK48 tf32 mma.sync GEMM
// with fused distance + min epilogue in accumulator registers.
// ---------------------------------------------------------------------------
__global__ __launch_bounds__(256, 2)
void dist_kernel(const float* __restrict__ x, const float* __restrict__ shp,
                 float* __restrict__ out)
{
    __shared__ uint32_t As[NS][APAD];      // shapelets, tf32 bits
    __shared__ float    xs[ND][XS_LEN];    // x window tile (raw -> tf32 in place)
    __shared__ float    wsq[TCH];          // window energy (exact fp32)
    __shared__ float    ssq[NS];           // shapelet energy (exact fp32)
    __shared__ int      minbuf[NS];

    const int tid   = threadIdx.x;
    const int bid   = blockIdx.x;
    const int b     = bid >> 7;
    const int chunk = bid & 127;
    const int t0    = chunk * TCH;

    // A: load shapelets, convert to tf32
    for (int i = tid; i < NS * NK; i += 256) {
        int s = i / NK, k = i - s * NK;
        As[s][k] = f2tf32(shp[i]);
    }
    // x tile (+halo), zero-pad past NT
    for (int i = tid; i < ND * XS_LEN; i += 256) {
        int d = i / XS_LEN, j = i - d * XS_LEN;
        int tg = t0 + j;
        xs[d][j] = (tg < NT) ? x[(b * ND + d) * NT + tg] : 0.0f;
    }
    if (tid < NS) {
        minbuf[tid] = 0x7F800000;
        const float* sr = shp + tid * NK;
        float a = 0.0f;
        #pragma unroll
        for (int k = 0; k < NK; k++) a = fmaf(sr[k], sr[k], a);
        ssq[tid] = a;
    }
    __syncthreads();

    // window energy from raw fp32 x
    if (tid < TCH) {
        float w = 0.0f;
        #pragma unroll
        for (int d = 0; d < ND; d++) {
            const float* xr = &xs[d][tid];
            #pragma unroll
            for (int l = 0; l < NL; l++) w = fmaf(xr[l], xr[l], w);
        }
        wsq[tid] = w;
    }
    __syncthreads();

    // convert xs to tf32 bits in place (each element touched by one thread)
    for (int i = tid; i < ND * XS_LEN; i += 256) {
        int d = i / XS_LEN, j = i - d * XS_LEN;
        uint32_t v = f2tf32(xs[d][j]);
        ((uint32_t*)&xs[d][0])[j] = v;
    }
    __syncthreads();

    const uint32_t* xsu = (const uint32_t*)&xs[0][0];   // [d*XS_LEN + j]

    const int lane = tid & 31;
    const int wrp  = tid >> 5;
    const int ws   = (wrp >> 1) * 32;   // warp s offset (4 groups)
    const int wt   = (wrp & 1) * 64;    // warp t offset (2 groups)
    const int g    = lane >> 2;         // groupID
    const int tig  = lane & 3;          // threadID in group

    float C[2][8][4];
    #pragma unroll
    for (int mt = 0; mt < 2; mt++)
        #pragma unroll
        for (int nt = 0; nt < 8; nt++)
            #pragma unroll
            for (int q = 0; q < 4; q++) C[mt][nt][q] = 0.0f;

    // K loop: 6 x k8
    #pragma unroll
    for (int kk = 0; kk < 6; kk++) {
        const int k0 = kk * 8;
        const int d  = k0 >> 4;          // channel (k8 block never crosses ch. boundary)
        const int lb = (k0 & 15) + tig;  // within-channel lag for this thread

        uint32_t a[2][4];
        #pragma unroll
        for (int mt = 0; mt < 2; mt++) {
            const int base = ws + mt * 16;
            a[mt][0] = As[base + g][k0 + tig];
            a[mt][1] = As[base + g + 8][k0 + tig];
            a[mt][2] = As[base + g][k0 + tig + 4];
            a[mt][3] = As[base + g + 8][k0 + tig + 4];
        }
        uint32_t bf[8][2];
        #pragma unroll
        for (int nt = 0; nt < 8; nt++) {
            const int tt = wt + nt * 8 + g;          // B col (t within chunk)
            bf[nt][0] = xsu[d * XS_LEN + tt + lb];
            bf[nt][1] = xsu[d * XS_LEN + tt + lb + 4];
        }
        #pragma unroll
        for (int mt = 0; mt < 2; mt++)
            #pragma unroll
            for (int nt = 0; nt < 8; nt++)
                mma_tf32(C[mt][nt], a[mt], bf[nt]);
    }

    // epilogue: dist = wsq[t] + ssq[s] - 2*corr ; min over t
    const int tvmax = TV - t0;          // cols < tvmax are valid
    const float INF = __int_as_float(0x7F800000);

    #pragma unroll
    for (int mt = 0; mt < 2; mt++) {
        const int base = ws + mt * 16;
        const float s0 = ssq[base + g];
        const float s1 = ssq[base + g + 8];
        float m0 = INF, m1 = INF;
        #pragma unroll
        for (int nt = 0; nt < 8; nt++) {
            const int t = wt + nt * 8 + 2 * tig;
            const float w0 = wsq[t], w1 = wsq[t + 1];
            float d00 = fmaf(-2.0f, C[mt][nt][0], w0 + s0);
            float d01 = fmaf(-2.0f, C[mt][nt][1], w1 + s0);
            float d10 = fmaf(-2.0f, C[mt][nt][2], w0 + s1);
            float d11 = fmaf(-2.0f, C[mt][nt][3], w1 + s1);
            if (t < tvmax)     { m0 = fminf(m0, d00); m1 = fminf(m1, d10); }
            if (t + 1 < tvmax) { m0 = fminf(m0, d01); m1 = fminf(m1, d11); }
        }
        m0 = fminf(m0, __shfl_xor_sync(0xFFFFFFFFu, m0, 1));
        m0 = fminf(m0, __shfl_xor_sync(0xFFFFFFFFu, m0, 2));
        m1 = fminf(m1, __shfl_xor_sync(0xFFFFFFFFu, m1, 1));
        m1 = fminf(m1, __shfl_xor_sync(0xFFFFFFFFu, m1, 2));
        if (tig == 0) {
            atomicMin(&minbuf[base + g],     __float_as_int(m0));
            atomicMin(&minbuf[base + g + 8], __float_as_int(m1));
        }
    }
    __syncthreads();

    if (tid < NS)
        atomicMin((int*)out + b * NS + tid, minbuf[tid]);
}

// ---------------------------------------------------------------------------
// MLP head: one block per batch row
// ---------------------------------------------------------------------------
__global__ __launch_bounds__(512)
void mlp_kernel(float* __restrict__ out,
                const float* __restrict__ W1, const float* __restrict__ b1,
                const float* __restrict__ W2, const float* __restrict__ b2)
{
    __shared__ float sd[NS];
    __shared__ float hbuf[NH];
    __shared__ float wpart[16];

    const int b   = blockIdx.x;
    const int tid = threadIdx.x;

    if (tid < NS) sd[tid] = out[b * NS + tid];
    __syncthreads();

    float a = b1[tid];
    #pragma unroll 8
    for (int k = 0; k < NS; k++)
        a = fmaf(sd[k], W1[tid * NS + k], a);
    hbuf[tid] = fmaxf(a, 0.0f);
    __syncthreads();

    const int lane = tid & 31;
    const int warp = tid >> 5;
    float* cls = out + NB * NS;

    for (int c = 0; c < NC; c++) {
        float p = hbuf[tid] * W2[c * NH + tid];
        #pragma unroll
        for (int o = 16; o > 0; o >>= 1)
            p += __shfl_down_sync(0xFFFFFFFFu, p, o);
        if (lane == 0) wpart[warp] = p;
        __syncthreads();
        if (tid < 16) {
            float q = wpart[tid];
            #pragma unroll
            for (int o = 8; o > 0; o >>= 1)
                q += __shfl_down_sync(0xFFFFu, q, o);
            if (tid == 0) cls[b * NC + c] = q + b2[c];
        }
        __syncthreads();
    }
}

// ---------------------------------------------------------------------------
extern "C" void kernel_launch(void* const* d_in, const int* in_sizes, int n_in,
                              void* d_out, int out_size)
{
    const float* x   = (const float*)d_in[0];
    const float* shp = (const float*)d_in[1];
    const float* W1  = (const float*)d_in[2];
    const float* b1  = (const float*)d_in[3];
    const float* W2  = (const float*)d_in[4];
    const float* b2  = (const float*)d_in[5];
    float* out = (float*)d_out;

    init_kernel<<<(NB * NS + 255) / 256, 256>>>(out);
    dist_kernel<<<NB * NCHUNK, 256>>>(x, shp, out);
    mlp_kernel<<<NB, NH>>>(out, W1, b1, W2, b2);
}

// round 7
// speedup vs baseline: 2.9419x; 1.6256x over previous
#include <cuda_runtime.h>
#include <cuda_bf16.h>
#include <cstdint>

// ---------------- problem constants ----------------
#define NS 128          // shapelets
#define ND 3            // channels
#define NL 16           // shapelet length
#define NK 48           // K
#define NH 512          // hidden
#define NC 10           // classes
#define NB 32           // batch
#define NT 16384        // time
#define TV (NT - NL + 1)   // 16369 valid positions
#define TCH 128
#define NCHUNK 128
#define CPB 9              // CTAs per batch row
#define GRID (NB * CPB)    // 288 persistent CTAs
#define XS_LEN (TCH + NL)  // 144
#define XS_TOT (ND * XS_LEN) // 432
#define APAD 52            // stride 52 == 20 mod 32 -> conflict-free frag loads

// partial mins: [b][cpb][s]
__device__ float g_part[NB * CPB * NS];

// ---------------- helpers ----------------
__device__ __forceinline__ uint32_t f2tf32(float f) {
    uint32_t r;
    asm("cvt.rna.tf32.f32 %0, %1;" : "=r"(r) : "f"(f));
    return r;
}

__device__ __forceinline__ void mma_tf32(float d[4], const uint32_t a[4], const uint32_t b[2]) {
    asm volatile(
        "mma.sync.aligned.m16n8k8.row.col.f32.tf32.tf32.f32 "
        "{%0,%1,%2,%3}, {%4,%5,%6,%7}, {%8,%9}, {%0,%1,%2,%3};"
        : "+f"(d[0]), "+f"(d[1]), "+f"(d[2]), "+f"(d[3])
        : "r"(a[0]), "r"(a[1]), "r"(a[2]), "r"(a[3]), "r"(b[0]), "r"(b[1]));
}

// ---------------------------------------------------------------------------
// dist: persistent CTA per (batch, chunk-stride). tf32 mma.sync 128x128xK48
// tiles; min kept in registers across chunks; one partial write at the end.
// ---------------------------------------------------------------------------
__global__ __launch_bounds__(256, 2)
void dist_kernel(const float* __restrict__ x, const float* __restrict__ shp)
{
    __shared__ uint32_t As[NS][APAD];        // shapelets tf32 (26624 B)
    __shared__ float    xs[2][XS_TOT];       // x tile, raw -> tf32 in place
    __shared__ float    wsq[2][TCH];
    __shared__ float    ssq[NS];
    __shared__ int      minbuf[NS];

    const int tid    = threadIdx.x;
    const int b      = blockIdx.x / CPB;
    const int cstart = blockIdx.x - b * CPB;
    const float* xb  = x + b * ND * NT;

    // ---- prologue: A tile + ssq once ----
    for (int i = tid; i < NS * NK; i += 256) {
        int s = i / NK, k = i - s * NK;
        As[s][k] = f2tf32(shp[i]);
    }
    if (tid < NS) {
        minbuf[tid] = 0x7F800000;
        const float* sr = shp + tid * NK;
        float a = 0.0f;
        #pragma unroll
        for (int k = 0; k < NK; k++) a = fmaf(sr[k], sr[k], a);
        ssq[tid] = a;
    }
    // first chunk raw
    {
        const int t0 = cstart * TCH;
        for (int i = tid; i < XS_TOT; i += 256) {
            int d = i / XS_LEN, j = i - d * XS_LEN;
            int tg = t0 + j;
            xs[0][i] = (tg < NT) ? xb[d * NT + tg] : 0.0f;
        }
    }
    __syncthreads();
    if (tid < TCH) {
        float w = 0.0f;
        #pragma unroll
        for (int d = 0; d < ND; d++) {
            const float* xr = &xs[0][d * XS_LEN + tid];
            #pragma unroll
            for (int l = 0; l < NL; l++) w = fmaf(xr[l], xr[l], w);
        }
        wsq[0][tid] = w;
    }
    __syncthreads();
    for (int i = tid; i < XS_TOT; i += 256)
        ((uint32_t*)xs[0])[i] = f2tf32(xs[0][i]);
    __syncthreads();

    // ---- warp/lane mapping ----
    const int lane = tid & 31;
    const int wrp  = tid >> 5;
    const int ws   = (wrp >> 1) * 32;
    const int wt   = (wrp & 1) * 64;
    const int g    = lane >> 2;
    const int tig  = lane & 3;

    // prefetch index split (432 elems over 256 threads)
    const int i0 = tid;
    const int d0 = i0 / XS_LEN, j0 = i0 - d0 * XS_LEN;
    const int i1 = tid + 256;
    const int d1 = i1 / XS_LEN, j1 = i1 - d1 * XS_LEN;   // valid iff i1 < 432

    const float INF = __int_as_float(0x7F800000);
    float mm[2][2] = {{INF, INF}, {INF, INF}};   // [mt][row 0/+8]

    int cur = 0;
    for (int chunk = cstart; chunk < NCHUNK; chunk += CPB) {
        const int t0 = chunk * TCH;
        const int cn = chunk + CPB;
        const int nxt = cur ^ 1;

        // prefetch next chunk raw into registers (overlaps mainloop)
        float pf0 = 0.0f, pf1 = 0.0f;
        if (cn < NCHUNK) {
            const int t0n = cn * TCH;
            int tg0 = t0n + j0;
            pf0 = (tg0 < NT) ? xb[d0 * NT + tg0] : 0.0f;
            if (i1 < XS_TOT) {
                int tg1 = t0n + j1;
                pf1 = (tg1 < NT) ? xb[d1 * NT + tg1] : 0.0f;
            }
        }

        const uint32_t* xsu = (const uint32_t*)xs[cur];
        const float* wq = wsq[cur];

        float C[2][8][4];
        #pragma unroll
        for (int mt = 0; mt < 2; mt++)
            #pragma unroll
            for (int nt = 0; nt < 8; nt++)
                #pragma unroll
                for (int q = 0; q < 4; q++) C[mt][nt][q] = 0.0f;

        #pragma unroll
        for (int kk = 0; kk < 6; kk++) {
            const int k0 = kk * 8;
            const int d  = k0 >> 4;
            const int lb = (k0 & 15) + tig;

            uint32_t a[2][4];
            #pragma unroll
            for (int mt = 0; mt < 2; mt++) {
                const int base = ws + mt * 16;
                a[mt][0] = As[base + g][k0 + tig];
                a[mt][1] = As[base + g + 8][k0 + tig];
                a[mt][2] = As[base + g][k0 + tig + 4];
                a[mt][3] = As[base + g + 8][k0 + tig + 4];
            }
            uint32_t bf[8][2];
            #pragma unroll
            for (int nt = 0; nt < 8; nt++) {
                const int tt = wt + nt * 8 + g;
                bf[nt][0] = xsu[d * XS_LEN + tt + lb];
                bf[nt][1] = xsu[d * XS_LEN + tt + lb + 4];
            }
            #pragma unroll
            for (int mt = 0; mt < 2; mt++)
                #pragma unroll
                for (int nt = 0; nt < 8; nt++)
                    mma_tf32(C[mt][nt], a[mt], bf[nt]);
        }

        // epilogue: min into persistent registers
        if (t0 + TCH <= TV) {       // fully valid chunk (all but the last)
            #pragma unroll
            for (int mt = 0; mt < 2; mt++) {
                const float s0 = ssq[ws + mt * 16 + g];
                const float s1 = ssq[ws + mt * 16 + g + 8];
                float m0 = INF, m1 = INF;
                #pragma unroll
                for (int nt = 0; nt < 8; nt++) {
                    const int t = wt + nt * 8 + 2 * tig;
                    const float w0 = wq[t], w1 = wq[t + 1];
                    m0 = fminf(m0, fminf(fmaf(-2.0f, C[mt][nt][0], w0 + s0),
                                         fmaf(-2.0f, C[mt][nt][1], w1 + s0)));
                    m1 = fminf(m1, fminf(fmaf(-2.0f, C[mt][nt][2], w0 + s1),
                                         fmaf(-2.0f, C[mt][nt][3], w1 + s1)));
                }
                mm[mt][0] = fminf(mm[mt][0], m0);
                mm[mt][1] = fminf(mm[mt][1], m1);
            }
        } else {
            const int tvmax = TV - t0;
            #pragma unroll
            for (int mt = 0; mt < 2; mt++) {
                const float s0 = ssq[ws + mt * 16 + g];
                const float s1 = ssq[ws + mt * 16 + g + 8];
                #pragma unroll
                for (int nt = 0; nt < 8; nt++) {
                    const int t = wt + nt * 8 + 2 * tig;
                    const float w0 = wq[t], w1 = wq[t + 1];
                    if (t < tvmax) {
                        mm[mt][0] = fminf(mm[mt][0], fmaf(-2.0f, C[mt][nt][0], w0 + s0));
                        mm[mt][1] = fminf(mm[mt][1], fmaf(-2.0f, C[mt][nt][2], w0 + s1));
                    }
                    if (t + 1 < tvmax) {
                        mm[mt][0] = fminf(mm[mt][0], fmaf(-2.0f, C[mt][nt][1], w1 + s0));
                        mm[mt][1] = fminf(mm[mt][1], fmaf(-2.0f, C[mt][nt][3], w1 + s1));
                    }
                }
            }
        }

        // stage next buffer
        if (cn < NCHUNK) {
            xs[nxt][i0] = pf0;
            if (i1 < XS_TOT) xs[nxt][i1] = pf1;
            __syncthreads();
            if (tid < TCH) {
                float w = 0.0f;
                #pragma unroll
                for (int d = 0; d < ND; d++) {
                    const float* xr = &xs[nxt][d * XS_LEN + tid];
                    #pragma unroll
                    for (int l = 0; l < NL; l++) w = fmaf(xr[l], xr[l], w);
                }
                wsq[nxt][tid] = w;
            }
            __syncthreads();
            for (int i = tid; i < XS_TOT; i += 256)
                ((uint32_t*)xs[nxt])[i] = f2tf32(xs[nxt][i]);
            __syncthreads();
            cur = nxt;
        }
    }

    // cross-lane (tig) min, then one smem atomic per row
    #pragma unroll
    for (int mt = 0; mt < 2; mt++) {
        float m0 = mm[mt][0], m1 = mm[mt][1];
        m0 = fminf(m0, __shfl_xor_sync(0xFFFFFFFFu, m0, 1));
        m0 = fminf(m0, __shfl_xor_sync(0xFFFFFFFFu, m0, 2));
        m1 = fminf(m1, __shfl_xor_sync(0xFFFFFFFFu, m1, 1));
        m1 = fminf(m1, __shfl_xor_sync(0xFFFFFFFFu, m1, 2));
        if (tig == 0) {
            atomicMin(&minbuf[ws + mt * 16 + g],     __float_as_int(m0));
            atomicMin(&minbuf[ws + mt * 16 + g + 8], __float_as_int(m1));
        }
    }
    __syncthreads();
    if (tid < NS)
        g_part[(b * CPB + cstart) * NS + tid] = __int_as_float(minbuf[tid]);
}

// ---------------------------------------------------------------------------
// MLP head + partial-min reduction: one block per batch row
// ---------------------------------------------------------------------------
__global__ __launch_bounds__(512)
void mlp_kernel(float* __restrict__ out,
                const float* __restrict__ W1, const float* __restrict__ b1,
                const float* __restrict__ W2, const float* __restrict__ b2)
{
    __shared__ float sd[NS];
    __shared__ float hbuf[NH];
    __shared__ float wpart[16];

    const int b   = blockIdx.x;
    const int tid = threadIdx.x;

    if (tid < NS) {
        float m = __int_as_float(0x7F800000);
        #pragma unroll
        for (int c = 0; c < CPB; c++)
            m = fminf(m, g_part[(b * CPB + c) * NS + tid]);
        out[b * NS + tid] = m;
        sd[tid] = m;
    }
    __syncthreads();

    float a = b1[tid];
    #pragma unroll 8
    for (int k = 0; k < NS; k++)
        a = fmaf(sd[k], W1[tid * NS + k], a);
    hbuf[tid] = fmaxf(a, 0.0f);
    __syncthreads();

    const int lane = tid & 31;
    const int warp = tid >> 5;
    float* cls = out + NB * NS;

    for (int c = 0; c < NC; c++) {
        float p = hbuf[tid] * W2[c * NH + tid];
        #pragma unroll
        for (int o = 16; o > 0; o >>= 1)
            p += __shfl_down_sync(0xFFFFFFFFu, p, o);
        if (lane == 0) wpart[warp] = p;
        __syncthreads();
        if (tid < 16) {
            float q = wpart[tid];
            #pragma unroll
            for (int o = 8; o > 0; o >>= 1)
                q += __shfl_down_sync(0xFFFFu, q, o);
            if (tid == 0) cls[b * NC + c] = q + b2[c];
        }
        __syncthreads();
    }
}

// ---------------------------------------------------------------------------
extern "C" void kernel_launch(void* const* d_in, const int* in_sizes, int n_in,
                              void* d_out, int out_size)
{
    const float* x   = (const float*)d_in[0];
    const float* shp = (const float*)d_in[1];
    const float* W1  = (const float*)d_in[2];
    const float* b1  = (const float*)d_in[3];
    const float* W2  = (const float*)d_in[4];
    const float* b2  = (const float*)d_in[5];
    float* out = (float*)d_out;

    dist_kernel<<<GRID, 256>>>(x, shp);
    mlp_kernel<<<NB, NH>>>(out, W1, b1, W2, b2);
}